// round 13
// baseline (speedup 1.0000x reference)
#include <cuda_runtime.h>
#include <cuda_fp16.h>
#include <math.h>
#include <stdint.h>

// Problem constants
#define BB   8
#define SS   2048
#define DD   1024
#define NN   1024
#define MM   (BB*SS)        // 16384
#define WSZ  (NN*DD)        // per weight matrix

// ---------------------------------------------------------------------------
// Scratch (no cudaMalloc allowed)
// ---------------------------------------------------------------------------
__device__ __align__(16) uint32_t g_u_re [(size_t)MM*NN];   // packed fp16 hi|lo
__device__ __align__(16) uint32_t g_u_im [(size_t)MM*NN];   // packed fp16 hi|lo
__device__ __align__(16) float g_y    [(size_t)MM*NN];
__device__ __align__(16) float g_g    [(size_t)MM*NN];
__device__ __align__(16) __half g_x_hi[(size_t)MM*DD];
__device__ __align__(16) __half g_x_lo[(size_t)MM*DD];
__device__ __align__(16) __half g_hsre_hi[(size_t)MM*NN];
__device__ __align__(16) __half g_hsre_lo[(size_t)MM*NN];
__device__ __align__(16) __half g_hsim_hi[(size_t)MM*NN];
__device__ __align__(16) __half g_hsim_lo[(size_t)MM*NN];
__device__ __align__(16) __half g_z_hi[(size_t)MM*NN];
__device__ __align__(16) __half g_z_lo[(size_t)MM*NN];
__device__ __align__(16) __half g_w   [(size_t)7*WSZ];      // single fp16 weights
__device__ float g_lam[3*NN];   // lam_re, lam_im, gamma

// ---------------------------------------------------------------------------
// Baseline-PTX helpers (compute_103-safe)
// ---------------------------------------------------------------------------
__device__ __forceinline__ uint32_t smem_u32(const void* p) {
    uint32_t a;
    asm("{ .reg .u64 t; cvta.to.shared.u64 t, %1; cvt.u32.u64 %0, t; }"
        : "=r"(a) : "l"(p));
    return a;
}
#define CP_ASYNC16(dst, src) \
    asm volatile("cp.async.cg.shared.global [%0], [%1], 16;" :: "r"(dst), "l"(src) : "memory")
#define CP_COMMIT() asm volatile("cp.async.commit_group;" ::: "memory")
#define CP_WAIT0()  asm volatile("cp.async.wait_group 0;"  ::: "memory")
#define CP_WAIT1()  asm volatile("cp.async.wait_group 1;"  ::: "memory")

#define LDMX4(r0,r1,r2,r3,addr) \
    asm volatile("ldmatrix.sync.aligned.m8n8.x4.shared.b16 {%0,%1,%2,%3}, [%4];" \
        : "=r"(r0),"=r"(r1),"=r"(r2),"=r"(r3) : "r"(addr))

#define MMA16816(c, a, b) \
    asm volatile("mma.sync.aligned.m16n8k16.row.col.f32.f16.f16.f32 " \
        "{%0,%1,%2,%3}, {%4,%5,%6,%7}, {%8,%9}, {%0,%1,%2,%3};" \
        : "+f"((c)[0]),"+f"((c)[1]),"+f"((c)[2]),"+f"((c)[3]) \
        : "r"((a)[0]),"r"((a)[1]),"r"((a)[2]),"r"((a)[3]), \
          "r"((b)[0]),"r"((b)[1]))

// ---------------------------------------------------------------------------
// 2-product GEMM core: 128x128 tile, BK=32, 256 threads (8 warps 2x4,
// warp tile 64x32). A split fp16 hi+lo (22-bit), W single fp16.
// Per K-chunk: (A_hi + A_lo) @ W  = 2 MMA products against one B tile.
// 3-stage cp.async pipeline (wait_group 1), 80B-padded rows, 2 CTAs/SM.
// ---------------------------------------------------------------------------
#define ROWB   80
#define TILEB  (128*ROWB)           // 10240 per tile
#define STAGEB (3*TILEB)            // 30720 per stage (Ahi, Alo, W)
#define GEMM_SMEM (3*STAGEB)        // 92160

struct Trip { const char *a_hi, *a_lo, *b; };

struct GemmCore {
    uint32_t sbase;
    int tid, lid, wid, wm, wn;
    size_t rowA0, rowB0;
    float acc[4][4][4];

    __device__ __forceinline__ void init(uint32_t sb, size_t ra0, size_t rb0) {
        sbase = sb;
        tid = threadIdx.x; lid = tid & 31; wid = tid >> 5;
        wm = (wid >> 2) * 64; wn = (wid & 3) * 32;
        rowA0 = ra0; rowB0 = rb0;
        #pragma unroll
        for (int i = 0; i < 4; i++)
            #pragma unroll
            for (int j = 0; j < 4; j++)
                #pragma unroll
                for (int q = 0; q < 4; q++) acc[i][j][q] = 0.0f;
    }

    __device__ __forceinline__ void load_stage(int stage, Trip t, int kb) {
        const uint32_t s0 = sbase + stage * STAGEB;
        #pragma unroll
        for (int i = 0; i < 2; i++) {
            int c = tid + i * 256;          // 0..511
            int r = c >> 2;                 // row 0..127
            int cc = (c & 3) * 16;          // 0/16/32/48
            size_t offA = (rowA0 + r) * 2048 + kb + cc;
            size_t offB = (rowB0 + r) * 2048 + kb + cc;
            uint32_t sp = r * ROWB + cc;
            CP_ASYNC16(s0 + sp,           t.a_hi + offA);
            CP_ASYNC16(s0 + TILEB + sp,   t.a_lo + offA);
            CP_ASYNC16(s0 + 2*TILEB + sp, t.b    + offB);
        }
    }

    __device__ __forceinline__ void compute_stage(int stage) {
        const uint32_t sAhi = sbase + stage * STAGEB;
        const uint32_t sAlo = sAhi + TILEB;
        const uint32_t sB   = sAhi + 2*TILEB;
        #pragma unroll
        for (int kh = 0; kh < 2; kh++) {
            const uint32_t kho = kh * 32 + ((lid & 16) ? 16 : 0);
            const uint32_t khb = kh * 32 + (((lid >> 3) & 1) ? 16 : 0);
            const uint32_t arow = (uint32_t)(wm + (lid & 15)) * ROWB;
            const uint32_t brow = (uint32_t)(wn + ((lid >> 4) & 1) * 8 + (lid & 7)) * ROWB;

            uint32_t b[4][2];
            #pragma unroll
            for (int np = 0; np < 2; np++) {
                uint32_t r0, r1, r2, r3;
                LDMX4(r0, r1, r2, r3, sB + brow + np*16*ROWB + khb);
                b[np*2][0] = r0; b[np*2][1] = r1;
                b[np*2+1][0] = r2; b[np*2+1][1] = r3;
            }
            uint32_t a[4][4];
            #pragma unroll
            for (int mt = 0; mt < 4; mt++)
                LDMX4(a[mt][0], a[mt][1], a[mt][2], a[mt][3],
                      sAhi + arow + mt*16*ROWB + kho);
            #pragma unroll
            for (int mt = 0; mt < 4; mt++)
                #pragma unroll
                for (int nt = 0; nt < 4; nt++)
                    MMA16816(acc[mt][nt], a[mt], b[nt]);    // A_hi * W
            #pragma unroll
            for (int mt = 0; mt < 4; mt++)
                LDMX4(a[mt][0], a[mt][1], a[mt][2], a[mt][3],
                      sAlo + arow + mt*16*ROWB + kho);
            #pragma unroll
            for (int mt = 0; mt < 4; mt++)
                #pragma unroll
                for (int nt = 0; nt < 4; nt++)
                    MMA16816(acc[mt][nt], a[mt], b[nt]);    // A_lo * W
        }
    }

    // 3-stage pipeline. Invariant at top of iter k: loads issued for stages
    // k and k+1; wait_group 1 guarantees stage-k resident while stage-(k+1)
    // stays in flight. Final iteration drains fully. Stage recycled at iter k
    // (load for k+2) was computed at iter k-1 — ordered by this iter's sync.
    __device__ __forceinline__ void run(const Trip* terms, int nterms) {
        const int KTOT = nterms * 32;
        load_stage(0, terms[0], 0);  CP_COMMIT();
        load_stage(1, terms[0], 64); CP_COMMIT();
        int s_load = 2, s_comp = 0;
        for (int k = 0; k < KTOT; k++) {
            if (k + 1 < KTOT) CP_WAIT1(); else CP_WAIT0();
            __syncthreads();
            int kn = k + 2;
            if (kn < KTOT) {
                load_stage(s_load, terms[kn >> 5], (kn & 31) * 64);
                CP_COMMIT();
                if (++s_load == 3) s_load = 0;
            }
            compute_stage(s_comp);
            if (++s_comp == 3) s_comp = 0;
        }
    }

    // packed=0: fp32 out; packed=1: fp16 hi|lo packed in uint32
    __device__ __forceinline__ void epilogue(void* Cv, int Nout, int tileN,
                                             const float* colscale, int packed) {
        const int blockRow = blockIdx.y * 128;
        const int blockCol = tileN * 128;
        #pragma unroll
        for (int nt = 0; nt < 4; nt++) {
            int j = blockCol + wn + nt * 8 + (lid & 3) * 2;
            float cs0 = colscale ? colscale[j]     : 1.0f;
            float cs1 = colscale ? colscale[j + 1] : 1.0f;
            #pragma unroll
            for (int mt = 0; mt < 4; mt++) {
                int r = blockRow + wm + mt * 16 + (lid >> 2);
                float v00 = acc[mt][nt][0] * cs0, v01 = acc[mt][nt][1] * cs1;
                float v10 = acc[mt][nt][2] * cs0, v11 = acc[mt][nt][3] * cs1;
                if (!packed) {
                    float* C = (float*)Cv;
                    *(float2*)&C[(size_t)r * Nout + j]       = make_float2(v00, v01);
                    *(float2*)&C[(size_t)(r + 8) * Nout + j] = make_float2(v10, v11);
                } else {
                    uint32_t* C = (uint32_t*)Cv;
                    __half h;
                    uint32_t p00, p01, p10, p11;
                    h = __float2half(v00);
                    p00 = (uint32_t)__half_as_ushort(h)
                        | ((uint32_t)__half_as_ushort(__float2half(v00 - __half2float(h))) << 16);
                    h = __float2half(v01);
                    p01 = (uint32_t)__half_as_ushort(h)
                        | ((uint32_t)__half_as_ushort(__float2half(v01 - __half2float(h))) << 16);
                    h = __float2half(v10);
                    p10 = (uint32_t)__half_as_ushort(h)
                        | ((uint32_t)__half_as_ushort(__float2half(v10 - __half2float(h))) << 16);
                    h = __float2half(v11);
                    p11 = (uint32_t)__half_as_ushort(h)
                        | ((uint32_t)__half_as_ushort(__float2half(v11 - __half2float(h))) << 16);
                    *(uint2*)&C[(size_t)r * Nout + j]       = make_uint2(p00, p01);
                    *(uint2*)&C[(size_t)(r + 8) * Nout + j] = make_uint2(p10, p11);
                }
            }
        }
    }
};

// ---------------------------------------------------------------------------
// Multi-job GEMM: shared A; grid.x = 8*njobs (tileN = blockIdx.x&7).
// ---------------------------------------------------------------------------
struct Job { const __half* b; void* out; const float* cs; int packed; };
struct MultiParams { const __half *a_hi, *a_lo; Job jobs[3]; };

__global__ __launch_bounds__(256, 2)
void gemm_multi(MultiParams p, int Nout)
{
    extern __shared__ char smem[];
    const int g = blockIdx.x >> 3;
    const int tileN = blockIdx.x & 7;
    const Job jb = p.jobs[g];

    GemmCore core;
    core.init(smem_u32(smem), (size_t)blockIdx.y * 128, (size_t)tileN * 128);

    Trip t = { (const char*)p.a_hi, (const char*)p.a_lo, (const char*)jb.b };
    core.run(&t, 1);
    core.epilogue(jb.out, Nout, tileN, jb.cs, jb.packed);
}

// ---------------------------------------------------------------------------
// 3-term GEMM (y): per-term trips.
// ---------------------------------------------------------------------------
struct GemmTerm { const __half *a_hi, *a_lo, *b; };
struct YParams { GemmTerm t[3]; };

__global__ __launch_bounds__(256, 2)
void gemm_y(YParams p, float* __restrict__ C, int Nout)
{
    extern __shared__ char smem[];
    const int tileN = blockIdx.x;

    GemmCore core;
    core.init(smem_u32(smem), (size_t)blockIdx.y * 128, (size_t)tileN * 128);

    Trip t[3];
    #pragma unroll
    for (int i = 0; i < 3; i++)
        t[i] = { (const char*)p.t[i].a_hi, (const char*)p.t[i].a_lo,
                 (const char*)p.t[i].b };
    core.run(t, 3);
    core.epilogue(C, Nout, tileN, nullptr, 0);
}

// ---------------------------------------------------------------------------
// Per-channel recurrence parameters
// ---------------------------------------------------------------------------
__global__ void params_kernel(const float* __restrict__ nu_log,
                              const float* __restrict__ theta_log)
{
    int n = blockIdx.x * blockDim.x + threadIdx.x;
    if (n < NN) {
        float mag   = expf(-expf(nu_log[n]));
        float phase = expf(theta_log[n]);
        g_lam[n]        = mag * cosf(phase);
        g_lam[NN + n]   = mag * sinf(phase);
        g_lam[2*NN + n] = sqrtf(fmaxf(1.0f - mag*mag, 0.0f));
    }
}

// ---------------------------------------------------------------------------
// Vectorized fp32 -> fp16 conversions
// ---------------------------------------------------------------------------
__device__ __forceinline__ uint32_t pack2h(float a, float b)
{
    return (uint32_t)__half_as_ushort(__float2half(a))
         | ((uint32_t)__half_as_ushort(__float2half(b)) << 16);
}
__device__ __forceinline__ void split4h(float4 f, uint2& h, uint2& l)
{
    __half h0 = __float2half(f.x), h1 = __float2half(f.y);
    __half h2 = __float2half(f.z), h3 = __float2half(f.w);
    h.x = (uint32_t)__half_as_ushort(h0) | ((uint32_t)__half_as_ushort(h1) << 16);
    h.y = (uint32_t)__half_as_ushort(h2) | ((uint32_t)__half_as_ushort(h3) << 16);
    l.x = pack2h(f.x - __half2float(h0), f.y - __half2float(h1));
    l.y = pack2h(f.z - __half2float(h2), f.w - __half2float(h3));
}

__global__ void cvt_x4(const float4* __restrict__ src,
                       uint2* __restrict__ hi, uint2* __restrict__ lo, int n4)
{
    int i = blockIdx.x * blockDim.x + threadIdx.x;
    if (i < n4) {
        uint2 h, l;
        split4h(src[i], h, l);
        hi[i] = h; lo[i] = l;
    }
}

// All 7 weights -> single fp16; slice 3 (C_im) negated.
struct WPtrs { const float* p[7]; };
__global__ void cvt_w4(WPtrs wp, uint2* __restrict__ out)
{
    int i = blockIdx.x * blockDim.x + threadIdx.x;      // 0 .. 7*WSZ/4-1
    int w = i / (WSZ/4);
    int j = i - w * (WSZ/4);
    float4 f = ((const float4*)wp.p[w])[j];
    if (w == 3) { f.x = -f.x; f.y = -f.y; f.z = -f.z; f.w = -f.w; }
    uint2 o;
    o.x = pack2h(f.x, f.y);
    o.y = pack2h(f.z, f.w);
    out[i] = o;
}

// ---------------------------------------------------------------------------
// Sequential complex recurrence, blocked by 16; u is packed fp16 hi|lo.
// ---------------------------------------------------------------------------
__device__ __forceinline__ float unpack_u(uint32_t p)
{
    return __half2float(__ushort_as_half((unsigned short)(p & 0xffffu)))
         + __half2float(__ushort_as_half((unsigned short)(p >> 16)));
}

__global__ void scan_kernel(const float* __restrict__ hid_re,
                            const float* __restrict__ hid_im,
                            float* __restrict__ out)
{
    int idx = blockIdx.x * blockDim.x + threadIdx.x;   // 0..B*N-1
    int b = idx >> 10;
    int n = idx & (NN - 1);
    const float lre = g_lam[n];
    const float lim = g_lam[NN + n];
    float hr = hid_re[idx];
    float hi = hid_im[idx];
    size_t off = (size_t)b * SS * NN + n;
    for (int s0 = 0; s0 < SS; s0 += 16) {
        uint32_t pur[16], pui[16];
        #pragma unroll
        for (int q = 0; q < 16; q++) {
            pur[q] = g_u_re[off + (size_t)q * NN];
            pui[q] = g_u_im[off + (size_t)q * NN];
        }
        #pragma unroll
        for (int q = 0; q < 16; q++) {
            float nr = fmaf(lre, hr, fmaf(-lim, hi, unpack_u(pur[q])));
            float ni = fmaf(lre, hi, fmaf( lim, hr, unpack_u(pui[q])));
            __half rh = __float2half(nr);
            __half ih = __float2half(ni);
            size_t o = off + (size_t)q * NN;
            g_hsre_hi[o] = rh;
            g_hsre_lo[o] = __float2half(nr - __half2float(rh));
            g_hsim_hi[o] = ih;
            g_hsim_lo[o] = __float2half(ni - __half2float(ih));
            hr = nr; hi = ni;
        }
        off += (size_t)16 * NN;
    }
    out[(size_t)MM * DD + idx]         = hr;   // hf_re
    out[(size_t)MM * DD + BB*NN + idx] = hi;   // hf_im
}

// ---------------------------------------------------------------------------
// Fused pointwise: z = gelu(LN(LN(y) * gelu(LN(g)))) -> fp16 hi/lo
// ---------------------------------------------------------------------------
__device__ __forceinline__ float gelu_exact(float x)
{
    return 0.5f * x * (1.0f + erff(x * 0.70710678118654752f));
}
__device__ __forceinline__ void block_stats(float v0, float v1, float v2, float v3,
                                            float* sh, float& mu, float& rstd)
{
    float s  = v0 + v1 + v2 + v3;
    float s2 = v0*v0 + v1*v1 + v2*v2 + v3*v3;
    #pragma unroll
    for (int o = 16; o > 0; o >>= 1) {
        s  += __shfl_xor_sync(0xffffffffu, s,  o);
        s2 += __shfl_xor_sync(0xffffffffu, s2, o);
    }
    int w = threadIdx.x >> 5, l = threadIdx.x & 31;
    if (l == 0) { sh[w] = s; sh[8 + w] = s2; }
    __syncthreads();
    float ts = 0.f, ts2 = 0.f;
    #pragma unroll
    for (int i = 0; i < 8; i++) { ts += sh[i]; ts2 += sh[8 + i]; }
    __syncthreads();
    mu = ts * (1.0f / NN);
    float var = ts2 * (1.0f / NN) - mu * mu;
    rstd = rsqrtf(var + 1e-5f);
}

__global__ __launch_bounds__(256)
void pointwise_kernel(const float* __restrict__ y, const float* __restrict__ g)
{
    __shared__ float sh[16];
    const size_t base = (size_t)blockIdx.x * NN;
    const int t = threadIdx.x;

    float yv[4], gv[4];
    #pragma unroll
    for (int q = 0; q < 4; q++) {
        yv[q] = y[base + t + q*256];
        gv[q] = g[base + t + q*256];
    }
    float mu, rstd;
    block_stats(yv[0], yv[1], yv[2], yv[3], sh, mu, rstd);
    #pragma unroll
    for (int q = 0; q < 4; q++) yv[q] = (yv[q] - mu) * rstd;
    block_stats(gv[0], gv[1], gv[2], gv[3], sh, mu, rstd);
    #pragma unroll
    for (int q = 0; q < 4; q++) gv[q] = gelu_exact((gv[q] - mu) * rstd);
    #pragma unroll
    for (int q = 0; q < 4; q++) yv[q] *= gv[q];
    block_stats(yv[0], yv[1], yv[2], yv[3], sh, mu, rstd);
    #pragma unroll
    for (int q = 0; q < 4; q++) {
        float z = gelu_exact((yv[q] - mu) * rstd);
        __half zh = __float2half(z);
        g_z_hi[base + t + q*256] = zh;
        g_z_lo[base + t + q*256] = __float2half(z - __half2float(zh));
    }
}

// ---------------------------------------------------------------------------
// Launch.  ncu capture lands on launch index 3 -> big gemm_multi there.
// ---------------------------------------------------------------------------
extern "C" void kernel_launch(void* const* d_in, const int* in_sizes, int n_in,
                              void* d_out, int out_size)
{
    const float* x         = (const float*)d_in[0];
    const float* hidden_re = (const float*)d_in[1];
    const float* hidden_im = (const float*)d_in[2];
    const float* nu_log    = (const float*)d_in[3];
    const float* theta_log = (const float*)d_in[4];
    float* out = (float*)d_out;

    uint32_t *u_re, *u_im;
    float *ybuf, *gbuf, *lam;
    __half *x_hi, *x_lo, *hsre_hi, *hsre_lo, *hsim_hi, *hsim_lo,
           *z_hi, *z_lo, *wbuf;
    cudaGetSymbolAddress((void**)&u_re,    g_u_re);
    cudaGetSymbolAddress((void**)&u_im,    g_u_im);
    cudaGetSymbolAddress((void**)&ybuf,    g_y);
    cudaGetSymbolAddress((void**)&gbuf,    g_g);
    cudaGetSymbolAddress((void**)&x_hi,    g_x_hi);
    cudaGetSymbolAddress((void**)&x_lo,    g_x_lo);
    cudaGetSymbolAddress((void**)&hsre_hi, g_hsre_hi);
    cudaGetSymbolAddress((void**)&hsre_lo, g_hsre_lo);
    cudaGetSymbolAddress((void**)&hsim_hi, g_hsim_hi);
    cudaGetSymbolAddress((void**)&hsim_lo, g_hsim_lo);
    cudaGetSymbolAddress((void**)&z_hi,    g_z_hi);
    cudaGetSymbolAddress((void**)&z_lo,    g_z_lo);
    cudaGetSymbolAddress((void**)&wbuf,    g_w);
    cudaGetSymbolAddress((void**)&lam,     g_lam);
    const float* gamma = lam + 2*NN;

    cudaFuncSetAttribute(gemm_multi, cudaFuncAttributeMaxDynamicSharedMemorySize, GEMM_SMEM);
    cudaFuncSetAttribute(gemm_y,     cudaFuncAttributeMaxDynamicSharedMemorySize, GEMM_SMEM);

    params_kernel<<<1, 1024>>>(nu_log, theta_log);                       // idx 0
    {
        int n4 = MM*DD/4;
        cvt_x4<<<(n4 + 255)/256, 256>>>((const float4*)x,
                                        (uint2*)x_hi, (uint2*)x_lo, n4); // idx 1
    }
    {
        WPtrs wp;
        for (int w = 0; w < 7; w++) wp.p[w] = (const float*)d_in[5 + w];
        cvt_w4<<<(7*WSZ/4 + 255)/256, 256>>>(wp, (uint2*)wbuf);          // idx 2
    }

    // idx 3 (ncu capture target): fused u_re / u_im / gate GEMM
    MultiParams mp;
    mp.a_hi = x_hi; mp.a_lo = x_lo;
    mp.jobs[0] = { wbuf + (size_t)0*WSZ, (void*)u_re, gamma,   1 };
    mp.jobs[1] = { wbuf + (size_t)1*WSZ, (void*)u_im, gamma,   1 };
    mp.jobs[2] = { wbuf + (size_t)5*WSZ, (void*)gbuf, nullptr, 0 };
    gemm_multi<<<dim3(24, MM/128), 256, GEMM_SMEM>>>(mp, NN);

    // idx 4: recurrence (writes hs hi/lo + final state)
    scan_kernel<<<(BB*NN)/256, 256>>>(hidden_re, hidden_im, out);

    // idx 5: y = hs_re@C_re^T - hs_im@C_im^T + x@D_skip^T  (C_im pre-negated)
    YParams py;
    py.t[0] = { hsre_hi, hsre_lo, wbuf + (size_t)2*WSZ };
    py.t[1] = { hsim_hi, hsim_lo, wbuf + (size_t)3*WSZ };
    py.t[2] = { x_hi,    x_lo,    wbuf + (size_t)4*WSZ };
    gemm_y<<<dim3(8, MM/128), 256, GEMM_SMEM>>>(py, ybuf, NN);

    // idx 6: fused LN/GELU chain -> z hi/lo
    pointwise_kernel<<<MM, 256>>>(ybuf, gbuf);

    // idx 7: out = z @ W_con^T
    MultiParams mo;
    mo.a_hi = z_hi; mo.a_lo = z_lo;
    mo.jobs[0] = { wbuf + (size_t)6*WSZ, (void*)out, nullptr, 0 };
    gemm_multi<<<dim3(8, MM/128), 256, GEMM_SMEM>>>(mo, DD);
}

// round 14
// speedup vs baseline: 1.0098x; 1.0098x over previous
#include <cuda_runtime.h>
#include <cuda_fp16.h>
#include <math.h>
#include <stdint.h>

// Problem constants
#define BB   8
#define SS   2048
#define DD   1024
#define NN   1024
#define MM   (BB*SS)        // 16384
#define WSZ  (NN*DD)        // per weight matrix

// ---------------------------------------------------------------------------
// Scratch (no cudaMalloc allowed)
// ---------------------------------------------------------------------------
__device__ __align__(16) uint32_t g_u_re [(size_t)MM*NN];   // packed fp16 hi|lo; reused as y2 (fp32) after scan
__device__ __align__(16) uint32_t g_u_im [(size_t)MM*NN];   // packed fp16 hi|lo
__device__ __align__(16) float g_y    [(size_t)MM*NN];
__device__ __align__(16) float g_g    [(size_t)MM*NN];
__device__ __align__(16) __half g_x_hi[(size_t)MM*DD];
__device__ __align__(16) __half g_x_lo[(size_t)MM*DD];
__device__ __align__(16) __half g_hsre_hi[(size_t)MM*NN];
__device__ __align__(16) __half g_hsre_lo[(size_t)MM*NN];
__device__ __align__(16) __half g_hsim_hi[(size_t)MM*NN];
__device__ __align__(16) __half g_hsim_lo[(size_t)MM*NN];
__device__ __align__(16) __half g_z_hi[(size_t)MM*NN];
__device__ __align__(16) __half g_z_lo[(size_t)MM*NN];
__device__ __align__(16) __half g_w   [(size_t)7*WSZ];      // single fp16 weights
__device__ float g_lam[3*NN];   // lam_re, lam_im, gamma

// ---------------------------------------------------------------------------
// Baseline-PTX helpers (compute_103-safe)
// ---------------------------------------------------------------------------
__device__ __forceinline__ uint32_t smem_u32(const void* p) {
    uint32_t a;
    asm("{ .reg .u64 t; cvta.to.shared.u64 t, %1; cvt.u32.u64 %0, t; }"
        : "=r"(a) : "l"(p));
    return a;
}
#define CP_ASYNC16(dst, src) \
    asm volatile("cp.async.cg.shared.global [%0], [%1], 16;" :: "r"(dst), "l"(src) : "memory")
#define CP_COMMIT() asm volatile("cp.async.commit_group;" ::: "memory")
#define CP_WAIT0()  asm volatile("cp.async.wait_group 0;"  ::: "memory")

#define LDMX4(r0,r1,r2,r3,addr) \
    asm volatile("ldmatrix.sync.aligned.m8n8.x4.shared.b16 {%0,%1,%2,%3}, [%4];" \
        : "=r"(r0),"=r"(r1),"=r"(r2),"=r"(r3) : "r"(addr))

#define MMA16816(c, a, b) \
    asm volatile("mma.sync.aligned.m16n8k16.row.col.f32.f16.f16.f32 " \
        "{%0,%1,%2,%3}, {%4,%5,%6,%7}, {%8,%9}, {%0,%1,%2,%3};" \
        : "+f"((c)[0]),"+f"((c)[1]),"+f"((c)[2]),"+f"((c)[3]) \
        : "r"((a)[0]),"r"((a)[1]),"r"((a)[2]),"r"((a)[3]), \
          "r"((b)[0]),"r"((b)[1]))

// ---------------------------------------------------------------------------
// 2-product GEMM core (R11 config): 128x128 tile, BK=32, 256 threads
// (8 warps 2x4, warp tile 64x32). A split fp16 hi+lo (22-bit), W single fp16.
// Per K-chunk: (A_hi + A_lo) @ W. Single-sync 2-stage cp.async double buffer,
// 80B-padded rows, 2 CTAs/SM.
// ---------------------------------------------------------------------------
#define ROWB   80
#define TILEB  (128*ROWB)           // 10240 per tile
#define STAGEB (3*TILEB)            // 30720 per stage (Ahi, Alo, W)
#define GEMM_SMEM (2*STAGEB)        // 61440

struct Trip { const char *a_hi, *a_lo, *b; };

struct GemmCore {
    uint32_t sbase;
    int tid, lid, wid, wm, wn;
    size_t rowA0, rowB0;
    float acc[4][4][4];

    __device__ __forceinline__ void init(uint32_t sb, size_t ra0, size_t rb0) {
        sbase = sb;
        tid = threadIdx.x; lid = tid & 31; wid = tid >> 5;
        wm = (wid >> 2) * 64; wn = (wid & 3) * 32;
        rowA0 = ra0; rowB0 = rb0;
        #pragma unroll
        for (int i = 0; i < 4; i++)
            #pragma unroll
            for (int j = 0; j < 4; j++)
                #pragma unroll
                for (int q = 0; q < 4; q++) acc[i][j][q] = 0.0f;
    }

    __device__ __forceinline__ void load_stage(int stage, Trip t, int kb) {
        const uint32_t s0 = sbase + stage * STAGEB;
        #pragma unroll
        for (int i = 0; i < 2; i++) {
            int c = tid + i * 256;          // 0..511
            int r = c >> 2;                 // row 0..127
            int cc = (c & 3) * 16;          // 0/16/32/48
            size_t offA = (rowA0 + r) * 2048 + kb + cc;
            size_t offB = (rowB0 + r) * 2048 + kb + cc;
            uint32_t sp = r * ROWB + cc;
            CP_ASYNC16(s0 + sp,           t.a_hi + offA);
            CP_ASYNC16(s0 + TILEB + sp,   t.a_lo + offA);
            CP_ASYNC16(s0 + 2*TILEB + sp, t.b    + offB);
        }
    }

    __device__ __forceinline__ void compute_stage(int stage) {
        const uint32_t sAhi = sbase + stage * STAGEB;
        const uint32_t sAlo = sAhi + TILEB;
        const uint32_t sB   = sAhi + 2*TILEB;
        #pragma unroll
        for (int kh = 0; kh < 2; kh++) {
            const uint32_t kho = kh * 32 + ((lid & 16) ? 16 : 0);
            const uint32_t khb = kh * 32 + (((lid >> 3) & 1) ? 16 : 0);
            const uint32_t arow = (uint32_t)(wm + (lid & 15)) * ROWB;
            const uint32_t brow = (uint32_t)(wn + ((lid >> 4) & 1) * 8 + (lid & 7)) * ROWB;

            uint32_t b[4][2];
            #pragma unroll
            for (int np = 0; np < 2; np++) {
                uint32_t r0, r1, r2, r3;
                LDMX4(r0, r1, r2, r3, sB + brow + np*16*ROWB + khb);
                b[np*2][0] = r0; b[np*2][1] = r1;
                b[np*2+1][0] = r2; b[np*2+1][1] = r3;
            }
            uint32_t a[4][4];
            #pragma unroll
            for (int mt = 0; mt < 4; mt++)
                LDMX4(a[mt][0], a[mt][1], a[mt][2], a[mt][3],
                      sAhi + arow + mt*16*ROWB + kho);
            #pragma unroll
            for (int mt = 0; mt < 4; mt++)
                #pragma unroll
                for (int nt = 0; nt < 4; nt++)
                    MMA16816(acc[mt][nt], a[mt], b[nt]);    // A_hi * W
            #pragma unroll
            for (int mt = 0; mt < 4; mt++)
                LDMX4(a[mt][0], a[mt][1], a[mt][2], a[mt][3],
                      sAlo + arow + mt*16*ROWB + kho);
            #pragma unroll
            for (int mt = 0; mt < 4; mt++)
                #pragma unroll
                for (int nt = 0; nt < 4; nt++)
                    MMA16816(acc[mt][nt], a[mt], b[nt]);    // A_lo * W
        }
    }

    // Process global K-step range [s0, s1): term = s>>5, kb = (s&31)*64.
    __device__ __forceinline__ void run(const Trip* terms, int s0, int s1) {
        load_stage(0, terms[s0 >> 5], (s0 & 31) * 64); CP_COMMIT();
        for (int k = s0; k < s1; k++) {
            CP_WAIT0();
            __syncthreads();
            int kn = k + 1;
            if (kn < s1) {
                load_stage(kn & 1, terms[kn >> 5], (kn & 31) * 64);
                CP_COMMIT();
            }
            compute_stage(k & 1);
        }
    }

    // packed=0: fp32 out; packed=1: fp16 hi|lo packed in uint32
    __device__ __forceinline__ void epilogue(void* Cv, int Nout, int tileN,
                                             const float* colscale, int packed) {
        const int blockRow = blockIdx.y * 128;
        const int blockCol = tileN * 128;
        #pragma unroll
        for (int nt = 0; nt < 4; nt++) {
            int j = blockCol + wn + nt * 8 + (lid & 3) * 2;
            float cs0 = colscale ? colscale[j]     : 1.0f;
            float cs1 = colscale ? colscale[j + 1] : 1.0f;
            #pragma unroll
            for (int mt = 0; mt < 4; mt++) {
                int r = blockRow + wm + mt * 16 + (lid >> 2);
                float v00 = acc[mt][nt][0] * cs0, v01 = acc[mt][nt][1] * cs1;
                float v10 = acc[mt][nt][2] * cs0, v11 = acc[mt][nt][3] * cs1;
                if (!packed) {
                    float* C = (float*)Cv;
                    *(float2*)&C[(size_t)r * Nout + j]       = make_float2(v00, v01);
                    *(float2*)&C[(size_t)(r + 8) * Nout + j] = make_float2(v10, v11);
                } else {
                    uint32_t* C = (uint32_t*)Cv;
                    __half h;
                    uint32_t p00, p01, p10, p11;
                    h = __float2half(v00);
                    p00 = (uint32_t)__half_as_ushort(h)
                        | ((uint32_t)__half_as_ushort(__float2half(v00 - __half2float(h))) << 16);
                    h = __float2half(v01);
                    p01 = (uint32_t)__half_as_ushort(h)
                        | ((uint32_t)__half_as_ushort(__float2half(v01 - __half2float(h))) << 16);
                    h = __float2half(v10);
                    p10 = (uint32_t)__half_as_ushort(h)
                        | ((uint32_t)__half_as_ushort(__float2half(v10 - __half2float(h))) << 16);
                    h = __float2half(v11);
                    p11 = (uint32_t)__half_as_ushort(h)
                        | ((uint32_t)__half_as_ushort(__float2half(v11 - __half2float(h))) << 16);
                    *(uint2*)&C[(size_t)r * Nout + j]       = make_uint2(p00, p01);
                    *(uint2*)&C[(size_t)(r + 8) * Nout + j] = make_uint2(p10, p11);
                }
            }
        }
    }
};

// ---------------------------------------------------------------------------
// Multi-job GEMM: shared A; grid.x = 8*njobs (tileN = blockIdx.x&7).
// ---------------------------------------------------------------------------
struct Job { const __half* b; void* out; const float* cs; int packed; };
struct MultiParams { const __half *a_hi, *a_lo; Job jobs[3]; };

__global__ __launch_bounds__(256, 2)
void gemm_multi(MultiParams p, int Nout)
{
    extern __shared__ char smem[];
    const int g = blockIdx.x >> 3;
    const int tileN = blockIdx.x & 7;
    const Job jb = p.jobs[g];

    GemmCore core;
    core.init(smem_u32(smem), (size_t)blockIdx.y * 128, (size_t)tileN * 128);

    Trip t = { (const char*)p.a_hi, (const char*)p.a_lo, (const char*)jb.b };
    core.run(&t, 0, 32);
    core.epilogue(jb.out, Nout, tileN, jb.cs, jb.packed);
}

// ---------------------------------------------------------------------------
// 3-term GEMM (y), split-K=2: grid.x = 16; tileN = x&7, half = x>>3.
// Half 0 does global K-steps [0,48) -> C0; half 1 does [48,96) -> C1.
// ---------------------------------------------------------------------------
struct GemmTerm { const __half *a_hi, *a_lo, *b; };
struct YParams { GemmTerm t[3]; };

__global__ __launch_bounds__(256, 2)
void gemm_y(YParams p, float* __restrict__ C0, float* __restrict__ C1, int Nout)
{
    extern __shared__ char smem[];
    const int tileN = blockIdx.x & 7;
    const int half  = blockIdx.x >> 3;

    GemmCore core;
    core.init(smem_u32(smem), (size_t)blockIdx.y * 128, (size_t)tileN * 128);

    Trip t[3];
    #pragma unroll
    for (int i = 0; i < 3; i++)
        t[i] = { (const char*)p.t[i].a_hi, (const char*)p.t[i].a_lo,
                 (const char*)p.t[i].b };
    core.run(t, half * 48, half * 48 + 48);
    core.epilogue(half ? (void*)C1 : (void*)C0, Nout, tileN, nullptr, 0);
}

// ---------------------------------------------------------------------------
// Per-channel recurrence parameters
// ---------------------------------------------------------------------------
__global__ void params_kernel(const float* __restrict__ nu_log,
                              const float* __restrict__ theta_log)
{
    int n = blockIdx.x * blockDim.x + threadIdx.x;
    if (n < NN) {
        float mag   = expf(-expf(nu_log[n]));
        float phase = expf(theta_log[n]);
        g_lam[n]        = mag * cosf(phase);
        g_lam[NN + n]   = mag * sinf(phase);
        g_lam[2*NN + n] = sqrtf(fmaxf(1.0f - mag*mag, 0.0f));
    }
}

// ---------------------------------------------------------------------------
// Vectorized fp32 -> fp16 conversions
// ---------------------------------------------------------------------------
__device__ __forceinline__ uint32_t pack2h(float a, float b)
{
    return (uint32_t)__half_as_ushort(__float2half(a))
         | ((uint32_t)__half_as_ushort(__float2half(b)) << 16);
}
__device__ __forceinline__ void split4h(float4 f, uint2& h, uint2& l)
{
    __half h0 = __float2half(f.x), h1 = __float2half(f.y);
    __half h2 = __float2half(f.z), h3 = __float2half(f.w);
    h.x = (uint32_t)__half_as_ushort(h0) | ((uint32_t)__half_as_ushort(h1) << 16);
    h.y = (uint32_t)__half_as_ushort(h2) | ((uint32_t)__half_as_ushort(h3) << 16);
    l.x = pack2h(f.x - __half2float(h0), f.y - __half2float(h1));
    l.y = pack2h(f.z - __half2float(h2), f.w - __half2float(h3));
}

__global__ void cvt_x4(const float4* __restrict__ src,
                       uint2* __restrict__ hi, uint2* __restrict__ lo, int n4)
{
    int i = blockIdx.x * blockDim.x + threadIdx.x;
    if (i < n4) {
        uint2 h, l;
        split4h(src[i], h, l);
        hi[i] = h; lo[i] = l;
    }
}

// All 7 weights -> single fp16; slice 3 (C_im) negated.
struct WPtrs { const float* p[7]; };
__global__ void cvt_w4(WPtrs wp, uint2* __restrict__ out)
{
    int i = blockIdx.x * blockDim.x + threadIdx.x;      // 0 .. 7*WSZ/4-1
    int w = i / (WSZ/4);
    int j = i - w * (WSZ/4);
    float4 f = ((const float4*)wp.p[w])[j];
    if (w == 3) { f.x = -f.x; f.y = -f.y; f.z = -f.z; f.w = -f.w; }
    uint2 o;
    o.x = pack2h(f.x, f.y);
    o.y = pack2h(f.z, f.w);
    out[i] = o;
}

// ---------------------------------------------------------------------------
// Sequential complex recurrence, blocked by 16; u is packed fp16 hi|lo.
// ---------------------------------------------------------------------------
__device__ __forceinline__ float unpack_u(uint32_t p)
{
    return __half2float(__ushort_as_half((unsigned short)(p & 0xffffu)))
         + __half2float(__ushort_as_half((unsigned short)(p >> 16)));
}

__global__ void scan_kernel(const float* __restrict__ hid_re,
                            const float* __restrict__ hid_im,
                            float* __restrict__ out)
{
    int idx = blockIdx.x * blockDim.x + threadIdx.x;   // 0..B*N-1
    int b = idx >> 10;
    int n = idx & (NN - 1);
    const float lre = g_lam[n];
    const float lim = g_lam[NN + n];
    float hr = hid_re[idx];
    float hi = hid_im[idx];
    size_t off = (size_t)b * SS * NN + n;
    for (int s0 = 0; s0 < SS; s0 += 16) {
        uint32_t pur[16], pui[16];
        #pragma unroll
        for (int q = 0; q < 16; q++) {
            pur[q] = g_u_re[off + (size_t)q * NN];
            pui[q] = g_u_im[off + (size_t)q * NN];
        }
        #pragma unroll
        for (int q = 0; q < 16; q++) {
            float nr = fmaf(lre, hr, fmaf(-lim, hi, unpack_u(pur[q])));
            float ni = fmaf(lre, hi, fmaf( lim, hr, unpack_u(pui[q])));
            __half rh = __float2half(nr);
            __half ih = __float2half(ni);
            size_t o = off + (size_t)q * NN;
            g_hsre_hi[o] = rh;
            g_hsre_lo[o] = __float2half(nr - __half2float(rh));
            g_hsim_hi[o] = ih;
            g_hsim_lo[o] = __float2half(ni - __half2float(ih));
            hr = nr; hi = ni;
        }
        off += (size_t)16 * NN;
    }
    out[(size_t)MM * DD + idx]         = hr;   // hf_re
    out[(size_t)MM * DD + BB*NN + idx] = hi;   // hf_im
}

// ---------------------------------------------------------------------------
// Fused pointwise: y = y0 + y1 (split-K halves), then
// z = gelu(LN(LN(y) * gelu(LN(g)))) -> fp16 hi/lo
// ---------------------------------------------------------------------------
__device__ __forceinline__ float gelu_exact(float x)
{
    return 0.5f * x * (1.0f + erff(x * 0.70710678118654752f));
}
__device__ __forceinline__ void block_stats(float v0, float v1, float v2, float v3,
                                            float* sh, float& mu, float& rstd)
{
    float s  = v0 + v1 + v2 + v3;
    float s2 = v0*v0 + v1*v1 + v2*v2 + v3*v3;
    #pragma unroll
    for (int o = 16; o > 0; o >>= 1) {
        s  += __shfl_xor_sync(0xffffffffu, s,  o);
        s2 += __shfl_xor_sync(0xffffffffu, s2, o);
    }
    int w = threadIdx.x >> 5, l = threadIdx.x & 31;
    if (l == 0) { sh[w] = s; sh[8 + w] = s2; }
    __syncthreads();
    float ts = 0.f, ts2 = 0.f;
    #pragma unroll
    for (int i = 0; i < 8; i++) { ts += sh[i]; ts2 += sh[8 + i]; }
    __syncthreads();
    mu = ts * (1.0f / NN);
    float var = ts2 * (1.0f / NN) - mu * mu;
    rstd = rsqrtf(var + 1e-5f);
}

__global__ __launch_bounds__(256)
void pointwise_kernel(const float* __restrict__ y0, const float* __restrict__ y1,
                      const float* __restrict__ g)
{
    __shared__ float sh[16];
    const size_t base = (size_t)blockIdx.x * NN;
    const int t = threadIdx.x;

    float yv[4], gv[4];
    #pragma unroll
    for (int q = 0; q < 4; q++) {
        yv[q] = y0[base + t + q*256] + y1[base + t + q*256];
        gv[q] = g[base + t + q*256];
    }
    float mu, rstd;
    block_stats(yv[0], yv[1], yv[2], yv[3], sh, mu, rstd);
    #pragma unroll
    for (int q = 0; q < 4; q++) yv[q] = (yv[q] - mu) * rstd;
    block_stats(gv[0], gv[1], gv[2], gv[3], sh, mu, rstd);
    #pragma unroll
    for (int q = 0; q < 4; q++) gv[q] = gelu_exact((gv[q] - mu) * rstd);
    #pragma unroll
    for (int q = 0; q < 4; q++) yv[q] *= gv[q];
    block_stats(yv[0], yv[1], yv[2], yv[3], sh, mu, rstd);
    #pragma unroll
    for (int q = 0; q < 4; q++) {
        float z = gelu_exact((yv[q] - mu) * rstd);
        __half zh = __float2half(z);
        g_z_hi[base + t + q*256] = zh;
        g_z_lo[base + t + q*256] = __float2half(z - __half2float(zh));
    }
}

// ---------------------------------------------------------------------------
// Launch.  ncu capture lands on launch index 3 -> big gemm_multi there.
// ---------------------------------------------------------------------------
extern "C" void kernel_launch(void* const* d_in, const int* in_sizes, int n_in,
                              void* d_out, int out_size)
{
    const float* x         = (const float*)d_in[0];
    const float* hidden_re = (const float*)d_in[1];
    const float* hidden_im = (const float*)d_in[2];
    const float* nu_log    = (const float*)d_in[3];
    const float* theta_log = (const float*)d_in[4];
    float* out = (float*)d_out;

    uint32_t *u_re, *u_im;
    float *ybuf, *gbuf, *lam;
    __half *x_hi, *x_lo, *hsre_hi, *hsre_lo, *hsim_hi, *hsim_lo,
           *z_hi, *z_lo, *wbuf;
    cudaGetSymbolAddress((void**)&u_re,    g_u_re);
    cudaGetSymbolAddress((void**)&u_im,    g_u_im);
    cudaGetSymbolAddress((void**)&ybuf,    g_y);
    cudaGetSymbolAddress((void**)&gbuf,    g_g);
    cudaGetSymbolAddress((void**)&x_hi,    g_x_hi);
    cudaGetSymbolAddress((void**)&x_lo,    g_x_lo);
    cudaGetSymbolAddress((void**)&hsre_hi, g_hsre_hi);
    cudaGetSymbolAddress((void**)&hsre_lo, g_hsre_lo);
    cudaGetSymbolAddress((void**)&hsim_hi, g_hsim_hi);
    cudaGetSymbolAddress((void**)&hsim_lo, g_hsim_lo);
    cudaGetSymbolAddress((void**)&z_hi,    g_z_hi);
    cudaGetSymbolAddress((void**)&z_lo,    g_z_lo);
    cudaGetSymbolAddress((void**)&wbuf,    g_w);
    cudaGetSymbolAddress((void**)&lam,     g_lam);
    const float* gamma = lam + 2*NN;
    float* ybuf2 = (float*)u_re;   // u_re is dead after scan; reuse as split-K half

    cudaFuncSetAttribute(gemm_multi, cudaFuncAttributeMaxDynamicSharedMemorySize, GEMM_SMEM);
    cudaFuncSetAttribute(gemm_y,     cudaFuncAttributeMaxDynamicSharedMemorySize, GEMM_SMEM);

    params_kernel<<<1, 1024>>>(nu_log, theta_log);                       // idx 0
    {
        int n4 = MM*DD/4;
        cvt_x4<<<(n4 + 255)/256, 256>>>((const float4*)x,
                                        (uint2*)x_hi, (uint2*)x_lo, n4); // idx 1
    }
    {
        WPtrs wp;
        for (int w = 0; w < 7; w++) wp.p[w] = (const float*)d_in[5 + w];
        cvt_w4<<<(7*WSZ/4 + 255)/256, 256>>>(wp, (uint2*)wbuf);          // idx 2
    }

    // idx 3 (ncu capture target): fused u_re / u_im / gate GEMM
    MultiParams mp;
    mp.a_hi = x_hi; mp.a_lo = x_lo;
    mp.jobs[0] = { wbuf + (size_t)0*WSZ, (void*)u_re, gamma,   1 };
    mp.jobs[1] = { wbuf + (size_t)1*WSZ, (void*)u_im, gamma,   1 };
    mp.jobs[2] = { wbuf + (size_t)5*WSZ, (void*)gbuf, nullptr, 0 };
    gemm_multi<<<dim3(24, MM/128), 256, GEMM_SMEM>>>(mp, NN);

    // idx 4: recurrence (consumes u, writes hs hi/lo + final state)
    scan_kernel<<<(BB*NN)/256, 256>>>(hidden_re, hidden_im, out);

    // idx 5: y = hs_re@C_re^T - hs_im@C_im^T + x@D_skip^T, split-K=2
    YParams py;
    py.t[0] = { hsre_hi, hsre_lo, wbuf + (size_t)2*WSZ };
    py.t[1] = { hsim_hi, hsim_lo, wbuf + (size_t)3*WSZ };
    py.t[2] = { x_hi,    x_lo,    wbuf + (size_t)4*WSZ };
    gemm_y<<<dim3(16, MM/128), 256, GEMM_SMEM>>>(py, ybuf, ybuf2, NN);

    // idx 6: fused add + LN/GELU chain -> z hi/lo
    pointwise_kernel<<<MM, 256>>>(ybuf, ybuf2, gbuf);

    // idx 7: out = z @ W_con^T
    MultiParams mo;
    mo.a_hi = z_hi; mo.a_lo = z_lo;
    mo.jobs[0] = { wbuf + (size_t)6*WSZ, (void*)out, nullptr, 0 };
    gemm_multi<<<dim3(8, MM/128), 256, GEMM_SMEM>>>(mo, DD);
}

// round 15
// speedup vs baseline: 1.2467x; 1.2346x over previous
#include <cuda_runtime.h>
#include <cuda_fp16.h>
#include <math.h>
#include <stdint.h>

// Problem constants
#define BB   8
#define SS   2048
#define DD   1024
#define NN   1024
#define MM   (BB*SS)        // 16384
#define WSZ  (NN*DD)        // per weight matrix

// ---------------------------------------------------------------------------
// Scratch (no cudaMalloc allowed)
// ---------------------------------------------------------------------------
__device__ __align__(16) uint32_t g_u_re [(size_t)MM*NN];   // packed fp16 hi|lo
__device__ __align__(16) uint32_t g_u_im [(size_t)MM*NN];   // packed fp16 hi|lo
__device__ __align__(16) float g_y    [(size_t)MM*NN];
__device__ __align__(16) float g_g    [(size_t)MM*NN];
__device__ __align__(16) __half g_x_hi[(size_t)MM*DD];
__device__ __align__(16) __half g_x_lo[(size_t)MM*DD];
__device__ __align__(16) __half g_hsre[(size_t)MM*NN];      // single fp16
__device__ __align__(16) __half g_hsim[(size_t)MM*NN];      // single fp16
__device__ __align__(16) __half g_z   [(size_t)MM*NN];      // single fp16
__device__ __align__(16) __half g_w   [(size_t)7*WSZ];      // single fp16 weights
__device__ float g_lam[3*NN];   // lam_re, lam_im, gamma

// ---------------------------------------------------------------------------
// Baseline-PTX helpers (compute_103-safe)
// ---------------------------------------------------------------------------
__device__ __forceinline__ uint32_t smem_u32(const void* p) {
    uint32_t a;
    asm("{ .reg .u64 t; cvta.to.shared.u64 t, %1; cvt.u32.u64 %0, t; }"
        : "=r"(a) : "l"(p));
    return a;
}
#define CP_ASYNC16(dst, src) \
    asm volatile("cp.async.cg.shared.global [%0], [%1], 16;" :: "r"(dst), "l"(src) : "memory")
#define CP_COMMIT() asm volatile("cp.async.commit_group;" ::: "memory")
#define CP_WAIT0()  asm volatile("cp.async.wait_group 0;"  ::: "memory")

#define LDMX4(r0,r1,r2,r3,addr) \
    asm volatile("ldmatrix.sync.aligned.m8n8.x4.shared.b16 {%0,%1,%2,%3}, [%4];" \
        : "=r"(r0),"=r"(r1),"=r"(r2),"=r"(r3) : "r"(addr))

#define MMA16816(c, a, b) \
    asm volatile("mma.sync.aligned.m16n8k16.row.col.f32.f16.f16.f32 " \
        "{%0,%1,%2,%3}, {%4,%5,%6,%7}, {%8,%9}, {%0,%1,%2,%3};" \
        : "+f"((c)[0]),"+f"((c)[1]),"+f"((c)[2]),"+f"((c)[3]) \
        : "r"((a)[0]),"r"((a)[1]),"r"((a)[2]),"r"((a)[3]), \
          "r"((b)[0]),"r"((b)[1]))

// ---------------------------------------------------------------------------
// GEMM core (R11 config): 128x128 tile, BK=32, 256 threads (8 warps 2x4,
// warp tile 64x32). Optional A residual product (use_lo): acc += A_hi@W
// [+ A_lo@W]. Single-sync 2-stage cp.async double buffer, 80B-padded rows,
// 2 CTAs/SM.
// ---------------------------------------------------------------------------
#define ROWB   80
#define TILEB  (128*ROWB)           // 10240 per tile
#define STAGEB (3*TILEB)            // 30720 per stage (Ahi, Alo, W)
#define GEMM_SMEM (2*STAGEB)        // 61440

struct Trip { const char *a_hi, *a_lo, *b; };

struct GemmCore {
    uint32_t sbase;
    int tid, lid, wid, wm, wn;
    size_t rowA0, rowB0;
    float acc[4][4][4];

    __device__ __forceinline__ void init(uint32_t sb, size_t ra0, size_t rb0) {
        sbase = sb;
        tid = threadIdx.x; lid = tid & 31; wid = tid >> 5;
        wm = (wid >> 2) * 64; wn = (wid & 3) * 32;
        rowA0 = ra0; rowB0 = rb0;
        #pragma unroll
        for (int i = 0; i < 4; i++)
            #pragma unroll
            for (int j = 0; j < 4; j++)
                #pragma unroll
                for (int q = 0; q < 4; q++) acc[i][j][q] = 0.0f;
    }

    __device__ __forceinline__ void load_stage(int stage, Trip t, int kb,
                                               bool use_lo) {
        const uint32_t s0 = sbase + stage * STAGEB;
        #pragma unroll
        for (int i = 0; i < 2; i++) {
            int c = tid + i * 256;          // 0..511
            int r = c >> 2;                 // row 0..127
            int cc = (c & 3) * 16;          // 0/16/32/48
            size_t offA = (rowA0 + r) * 2048 + kb + cc;
            size_t offB = (rowB0 + r) * 2048 + kb + cc;
            uint32_t sp = r * ROWB + cc;
            CP_ASYNC16(s0 + sp,           t.a_hi + offA);
            if (use_lo) CP_ASYNC16(s0 + TILEB + sp, t.a_lo + offA);
            CP_ASYNC16(s0 + 2*TILEB + sp, t.b    + offB);
        }
    }

    __device__ __forceinline__ void compute_stage(int stage, bool use_lo) {
        const uint32_t sAhi = sbase + stage * STAGEB;
        const uint32_t sAlo = sAhi + TILEB;
        const uint32_t sB   = sAhi + 2*TILEB;
        #pragma unroll
        for (int kh = 0; kh < 2; kh++) {
            const uint32_t kho = kh * 32 + ((lid & 16) ? 16 : 0);
            const uint32_t khb = kh * 32 + (((lid >> 3) & 1) ? 16 : 0);
            const uint32_t arow = (uint32_t)(wm + (lid & 15)) * ROWB;
            const uint32_t brow = (uint32_t)(wn + ((lid >> 4) & 1) * 8 + (lid & 7)) * ROWB;

            uint32_t b[4][2];
            #pragma unroll
            for (int np = 0; np < 2; np++) {
                uint32_t r0, r1, r2, r3;
                LDMX4(r0, r1, r2, r3, sB + brow + np*16*ROWB + khb);
                b[np*2][0] = r0; b[np*2][1] = r1;
                b[np*2+1][0] = r2; b[np*2+1][1] = r3;
            }
            uint32_t a[4][4];
            #pragma unroll
            for (int mt = 0; mt < 4; mt++)
                LDMX4(a[mt][0], a[mt][1], a[mt][2], a[mt][3],
                      sAhi + arow + mt*16*ROWB + kho);
            #pragma unroll
            for (int mt = 0; mt < 4; mt++)
                #pragma unroll
                for (int nt = 0; nt < 4; nt++)
                    MMA16816(acc[mt][nt], a[mt], b[nt]);    // A_hi * W
            if (use_lo) {
                #pragma unroll
                for (int mt = 0; mt < 4; mt++)
                    LDMX4(a[mt][0], a[mt][1], a[mt][2], a[mt][3],
                          sAlo + arow + mt*16*ROWB + kho);
                #pragma unroll
                for (int mt = 0; mt < 4; mt++)
                    #pragma unroll
                    for (int nt = 0; nt < 4; nt++)
                        MMA16816(acc[mt][nt], a[mt], b[nt]);    // A_lo * W
            }
        }
    }

    __device__ __forceinline__ void run(const Trip* terms, int nterms,
                                        bool use_lo) {
        const int KTOT = nterms * 32;
        load_stage(0, terms[0], 0, use_lo); CP_COMMIT();
        for (int k = 0; k < KTOT; k++) {
            CP_WAIT0();
            __syncthreads();
            int kn = k + 1;
            if (kn < KTOT) {
                load_stage(kn & 1, terms[kn >> 5], (kn & 31) * 64, use_lo);
                CP_COMMIT();
            }
            compute_stage(k & 1, use_lo);
        }
    }

    // mode 0: fp32 out; 1: fp16 hi|lo packed in uint32; 2: single fp16
    __device__ __forceinline__ void epilogue(void* Cv, int Nout, int tileN,
                                             const float* colscale, int mode) {
        const int blockRow = blockIdx.y * 128;
        const int blockCol = tileN * 128;
        #pragma unroll
        for (int nt = 0; nt < 4; nt++) {
            int j = blockCol + wn + nt * 8 + (lid & 3) * 2;
            float cs0 = colscale ? colscale[j]     : 1.0f;
            float cs1 = colscale ? colscale[j + 1] : 1.0f;
            #pragma unroll
            for (int mt = 0; mt < 4; mt++) {
                int r = blockRow + wm + mt * 16 + (lid >> 2);
                float v00 = acc[mt][nt][0] * cs0, v01 = acc[mt][nt][1] * cs1;
                float v10 = acc[mt][nt][2] * cs0, v11 = acc[mt][nt][3] * cs1;
                if (mode == 0) {
                    float* C = (float*)Cv;
                    *(float2*)&C[(size_t)r * Nout + j]       = make_float2(v00, v01);
                    *(float2*)&C[(size_t)(r + 8) * Nout + j] = make_float2(v10, v11);
                } else if (mode == 1) {
                    uint32_t* C = (uint32_t*)Cv;
                    __half h;
                    uint32_t p00, p01, p10, p11;
                    h = __float2half(v00);
                    p00 = (uint32_t)__half_as_ushort(h)
                        | ((uint32_t)__half_as_ushort(__float2half(v00 - __half2float(h))) << 16);
                    h = __float2half(v01);
                    p01 = (uint32_t)__half_as_ushort(h)
                        | ((uint32_t)__half_as_ushort(__float2half(v01 - __half2float(h))) << 16);
                    h = __float2half(v10);
                    p10 = (uint32_t)__half_as_ushort(h)
                        | ((uint32_t)__half_as_ushort(__float2half(v10 - __half2float(h))) << 16);
                    h = __float2half(v11);
                    p11 = (uint32_t)__half_as_ushort(h)
                        | ((uint32_t)__half_as_ushort(__float2half(v11 - __half2float(h))) << 16);
                    *(uint2*)&C[(size_t)r * Nout + j]       = make_uint2(p00, p01);
                    *(uint2*)&C[(size_t)(r + 8) * Nout + j] = make_uint2(p10, p11);
                } else {
                    __half* C = (__half*)Cv;
                    __half2 u = __floats2half2_rn(v00, v01);
                    __half2 v = __floats2half2_rn(v10, v11);
                    *(__half2*)&C[(size_t)r * Nout + j]       = u;
                    *(__half2*)&C[(size_t)(r + 8) * Nout + j] = v;
                }
            }
        }
    }
};

// ---------------------------------------------------------------------------
// Multi-job GEMM: shared A; grid.x = 8*njobs (tileN = blockIdx.x&7).
// ---------------------------------------------------------------------------
struct Job { const __half* b; void* out; const float* cs; int mode; };
struct MultiParams { const __half *a_hi, *a_lo; Job jobs[3]; int use_lo; };

__global__ __launch_bounds__(256, 2)
void gemm_multi(MultiParams p, int Nout)
{
    extern __shared__ char smem[];
    const int g = blockIdx.x >> 3;
    const int tileN = blockIdx.x & 7;
    const Job jb = p.jobs[g];

    GemmCore core;
    core.init(smem_u32(smem), (size_t)blockIdx.y * 128, (size_t)tileN * 128);

    Trip t = { (const char*)p.a_hi, (const char*)p.a_lo, (const char*)jb.b };
    core.run(&t, 1, p.use_lo != 0);
    core.epilogue(jb.out, Nout, tileN, jb.cs, jb.mode);
}

// ---------------------------------------------------------------------------
// 3-term GEMM (y): hi-only products (A residuals dropped).
// ---------------------------------------------------------------------------
struct GemmTerm { const __half *a_hi, *b; };
struct YParams { GemmTerm t[3]; };

__global__ __launch_bounds__(256, 2)
void gemm_y(YParams p, float* __restrict__ C, int Nout)
{
    extern __shared__ char smem[];
    const int tileN = blockIdx.x;

    GemmCore core;
    core.init(smem_u32(smem), (size_t)blockIdx.y * 128, (size_t)tileN * 128);

    Trip t[3];
    #pragma unroll
    for (int i = 0; i < 3; i++)
        t[i] = { (const char*)p.t[i].a_hi, (const char*)p.t[i].a_hi,
                 (const char*)p.t[i].b };
    core.run(t, 3, false);
    core.epilogue(C, Nout, tileN, nullptr, 0);
}

// ---------------------------------------------------------------------------
// Per-channel recurrence parameters
// ---------------------------------------------------------------------------
__global__ void params_kernel(const float* __restrict__ nu_log,
                              const float* __restrict__ theta_log)
{
    int n = blockIdx.x * blockDim.x + threadIdx.x;
    if (n < NN) {
        float mag   = expf(-expf(nu_log[n]));
        float phase = expf(theta_log[n]);
        g_lam[n]        = mag * cosf(phase);
        g_lam[NN + n]   = mag * sinf(phase);
        g_lam[2*NN + n] = sqrtf(fmaxf(1.0f - mag*mag, 0.0f));
    }
}

// ---------------------------------------------------------------------------
// Vectorized fp32 -> fp16 conversions
// ---------------------------------------------------------------------------
__device__ __forceinline__ uint32_t pack2h(float a, float b)
{
    return (uint32_t)__half_as_ushort(__float2half(a))
         | ((uint32_t)__half_as_ushort(__float2half(b)) << 16);
}
__device__ __forceinline__ void split4h(float4 f, uint2& h, uint2& l)
{
    __half h0 = __float2half(f.x), h1 = __float2half(f.y);
    __half h2 = __float2half(f.z), h3 = __float2half(f.w);
    h.x = (uint32_t)__half_as_ushort(h0) | ((uint32_t)__half_as_ushort(h1) << 16);
    h.y = (uint32_t)__half_as_ushort(h2) | ((uint32_t)__half_as_ushort(h3) << 16);
    l.x = pack2h(f.x - __half2float(h0), f.y - __half2float(h1));
    l.y = pack2h(f.z - __half2float(h2), f.w - __half2float(h3));
}

__global__ void cvt_x4(const float4* __restrict__ src,
                       uint2* __restrict__ hi, uint2* __restrict__ lo, int n4)
{
    int i = blockIdx.x * blockDim.x + threadIdx.x;
    if (i < n4) {
        uint2 h, l;
        split4h(src[i], h, l);
        hi[i] = h; lo[i] = l;
    }
}

// All 7 weights -> single fp16; slice 3 (C_im) negated.
struct WPtrs { const float* p[7]; };
__global__ void cvt_w4(WPtrs wp, uint2* __restrict__ out)
{
    int i = blockIdx.x * blockDim.x + threadIdx.x;      // 0 .. 7*WSZ/4-1
    int w = i / (WSZ/4);
    int j = i - w * (WSZ/4);
    float4 f = ((const float4*)wp.p[w])[j];
    if (w == 3) { f.x = -f.x; f.y = -f.y; f.z = -f.z; f.w = -f.w; }
    uint2 o;
    o.x = pack2h(f.x, f.y);
    o.y = pack2h(f.z, f.w);
    out[i] = o;
}

// ---------------------------------------------------------------------------
// Sequential complex recurrence, blocked by 16; u is packed fp16 hi|lo;
// hs written as single fp16.
// ---------------------------------------------------------------------------
__device__ __forceinline__ float unpack_u(uint32_t p)
{
    return __half2float(__ushort_as_half((unsigned short)(p & 0xffffu)))
         + __half2float(__ushort_as_half((unsigned short)(p >> 16)));
}

__global__ void scan_kernel(const float* __restrict__ hid_re,
                            const float* __restrict__ hid_im,
                            float* __restrict__ out)
{
    int idx = blockIdx.x * blockDim.x + threadIdx.x;   // 0..B*N-1
    int b = idx >> 10;
    int n = idx & (NN - 1);
    const float lre = g_lam[n];
    const float lim = g_lam[NN + n];
    float hr = hid_re[idx];
    float hi = hid_im[idx];
    size_t off = (size_t)b * SS * NN + n;
    for (int s0 = 0; s0 < SS; s0 += 16) {
        uint32_t pur[16], pui[16];
        #pragma unroll
        for (int q = 0; q < 16; q++) {
            pur[q] = g_u_re[off + (size_t)q * NN];
            pui[q] = g_u_im[off + (size_t)q * NN];
        }
        #pragma unroll
        for (int q = 0; q < 16; q++) {
            float nr = fmaf(lre, hr, fmaf(-lim, hi, unpack_u(pur[q])));
            float ni = fmaf(lre, hi, fmaf( lim, hr, unpack_u(pui[q])));
            size_t o = off + (size_t)q * NN;
            g_hsre[o] = __float2half(nr);
            g_hsim[o] = __float2half(ni);
            hr = nr; hi = ni;
        }
        off += (size_t)16 * NN;
    }
    out[(size_t)MM * DD + idx]         = hr;   // hf_re
    out[(size_t)MM * DD + BB*NN + idx] = hi;   // hf_im
}

// ---------------------------------------------------------------------------
// Fused pointwise: z = gelu(LN(LN(y) * gelu(LN(g)))) -> single fp16
// ---------------------------------------------------------------------------
__device__ __forceinline__ float gelu_exact(float x)
{
    return 0.5f * x * (1.0f + erff(x * 0.70710678118654752f));
}
__device__ __forceinline__ void block_stats(float v0, float v1, float v2, float v3,
                                            float* sh, float& mu, float& rstd)
{
    float s  = v0 + v1 + v2 + v3;
    float s2 = v0*v0 + v1*v1 + v2*v2 + v3*v3;
    #pragma unroll
    for (int o = 16; o > 0; o >>= 1) {
        s  += __shfl_xor_sync(0xffffffffu, s,  o);
        s2 += __shfl_xor_sync(0xffffffffu, s2, o);
    }
    int w = threadIdx.x >> 5, l = threadIdx.x & 31;
    if (l == 0) { sh[w] = s; sh[8 + w] = s2; }
    __syncthreads();
    float ts = 0.f, ts2 = 0.f;
    #pragma unroll
    for (int i = 0; i < 8; i++) { ts += sh[i]; ts2 += sh[8 + i]; }
    __syncthreads();
    mu = ts * (1.0f / NN);
    float var = ts2 * (1.0f / NN) - mu * mu;
    rstd = rsqrtf(var + 1e-5f);
}

__global__ __launch_bounds__(256)
void pointwise_kernel(const float* __restrict__ y, const float* __restrict__ g)
{
    __shared__ float sh[16];
    const size_t base = (size_t)blockIdx.x * NN;
    const int t = threadIdx.x;

    float yv[4], gv[4];
    #pragma unroll
    for (int q = 0; q < 4; q++) {
        yv[q] = y[base + t + q*256];
        gv[q] = g[base + t + q*256];
    }
    float mu, rstd;
    block_stats(yv[0], yv[1], yv[2], yv[3], sh, mu, rstd);
    #pragma unroll
    for (int q = 0; q < 4; q++) yv[q] = (yv[q] - mu) * rstd;
    block_stats(gv[0], gv[1], gv[2], gv[3], sh, mu, rstd);
    #pragma unroll
    for (int q = 0; q < 4; q++) gv[q] = gelu_exact((gv[q] - mu) * rstd);
    #pragma unroll
    for (int q = 0; q < 4; q++) yv[q] *= gv[q];
    block_stats(yv[0], yv[1], yv[2], yv[3], sh, mu, rstd);
    #pragma unroll
    for (int q = 0; q < 4; q++)
        g_z[base + t + q*256] = __float2half(gelu_exact((yv[q] - mu) * rstd));
}

// ---------------------------------------------------------------------------
// Launch.  ncu capture lands on launch index 3 -> big gemm_multi there.
// ---------------------------------------------------------------------------
extern "C" void kernel_launch(void* const* d_in, const int* in_sizes, int n_in,
                              void* d_out, int out_size)
{
    const float* x         = (const float*)d_in[0];
    const float* hidden_re = (const float*)d_in[1];
    const float* hidden_im = (const float*)d_in[2];
    const float* nu_log    = (const float*)d_in[3];
    const float* theta_log = (const float*)d_in[4];
    float* out = (float*)d_out;

    uint32_t *u_re, *u_im;
    float *ybuf, *gbuf, *lam;
    __half *x_hi, *x_lo, *hsre, *hsim, *zbuf, *wbuf;
    cudaGetSymbolAddress((void**)&u_re, g_u_re);
    cudaGetSymbolAddress((void**)&u_im, g_u_im);
    cudaGetSymbolAddress((void**)&ybuf, g_y);
    cudaGetSymbolAddress((void**)&gbuf, g_g);
    cudaGetSymbolAddress((void**)&x_hi, g_x_hi);
    cudaGetSymbolAddress((void**)&x_lo, g_x_lo);
    cudaGetSymbolAddress((void**)&hsre, g_hsre);
    cudaGetSymbolAddress((void**)&hsim, g_hsim);
    cudaGetSymbolAddress((void**)&zbuf, g_z);
    cudaGetSymbolAddress((void**)&wbuf, g_w);
    cudaGetSymbolAddress((void**)&lam,  g_lam);
    const float* gamma = lam + 2*NN;

    cudaFuncSetAttribute(gemm_multi, cudaFuncAttributeMaxDynamicSharedMemorySize, GEMM_SMEM);
    cudaFuncSetAttribute(gemm_y,     cudaFuncAttributeMaxDynamicSharedMemorySize, GEMM_SMEM);

    params_kernel<<<1, 1024>>>(nu_log, theta_log);                       // idx 0
    {
        int n4 = MM*DD/4;
        cvt_x4<<<(n4 + 255)/256, 256>>>((const float4*)x,
                                        (uint2*)x_hi, (uint2*)x_lo, n4); // idx 1
    }
    {
        WPtrs wp;
        for (int w = 0; w < 7; w++) wp.p[w] = (const float*)d_in[5 + w];
        cvt_w4<<<(7*WSZ/4 + 255)/256, 256>>>(wp, (uint2*)wbuf);          // idx 2
    }

    // idx 3 (ncu capture target): fused u_re / u_im / gate GEMM (2-product)
    MultiParams mp;
    mp.a_hi = x_hi; mp.a_lo = x_lo; mp.use_lo = 1;
    mp.jobs[0] = { wbuf + (size_t)0*WSZ, (void*)u_re, gamma,   1 };
    mp.jobs[1] = { wbuf + (size_t)1*WSZ, (void*)u_im, gamma,   1 };
    mp.jobs[2] = { wbuf + (size_t)5*WSZ, (void*)gbuf, nullptr, 0 };
    gemm_multi<<<dim3(24, MM/128), 256, GEMM_SMEM>>>(mp, NN);

    // idx 4: recurrence (consumes u, writes hs single-fp16 + final state)
    scan_kernel<<<(BB*NN)/256, 256>>>(hidden_re, hidden_im, out);

    // idx 5: y = hs_re@C_re^T - hs_im@C_im^T + x@D_skip^T (hi-only products)
    YParams py;
    py.t[0] = { hsre, wbuf + (size_t)2*WSZ };
    py.t[1] = { hsim, wbuf + (size_t)3*WSZ };
    py.t[2] = { x_hi, wbuf + (size_t)4*WSZ };
    gemm_y<<<dim3(8, MM/128), 256, GEMM_SMEM>>>(py, ybuf, NN);

    // idx 6: fused LN/GELU chain -> z single fp16
    pointwise_kernel<<<MM, 256>>>(ybuf, gbuf);

    // idx 7: out = z @ W_con^T (hi-only product)
    MultiParams mo;
    mo.a_hi = zbuf; mo.a_lo = zbuf; mo.use_lo = 0;
    mo.jobs[0] = { wbuf + (size_t)6*WSZ, (void*)out, nullptr, 0 };
    gemm_multi<<<dim3(8, MM/128), 256, GEMM_SMEM>>>(mo, DD);
}

// round 17
// speedup vs baseline: 1.6574x; 1.3294x over previous
#include <cuda_runtime.h>
#include <cuda_fp16.h>
#include <math.h>
#include <stdint.h>

// Problem constants
#define BB   8
#define SS   2048
#define DD   1024
#define NN   1024
#define MM   (BB*SS)        // 16384
#define WSZ  (NN*DD)        // per weight matrix

// ---------------------------------------------------------------------------
// Scratch (no cudaMalloc allowed)
// ---------------------------------------------------------------------------
__device__ __align__(16) __half g_u_re[(size_t)MM*NN];      // single fp16
__device__ __align__(16) __half g_u_im[(size_t)MM*NN];      // single fp16
__device__ __align__(16) float g_y [(size_t)MM*NN];
__device__ __align__(16) float g_g [(size_t)MM*NN];
__device__ __align__(16) __half g_x   [(size_t)MM*DD];      // single fp16
__device__ __align__(16) __half g_hsre[(size_t)MM*NN];      // single fp16
__device__ __align__(16) __half g_hsim[(size_t)MM*NN];      // single fp16
__device__ __align__(16) __half g_z   [(size_t)MM*NN];      // single fp16
__device__ __align__(16) __half g_w   [(size_t)7*WSZ];      // single fp16 weights
__device__ float g_lam[3*NN];   // lam_re, lam_im, gamma

// ---------------------------------------------------------------------------
// Baseline-PTX helpers (compute_103-safe)
// ---------------------------------------------------------------------------
__device__ __forceinline__ uint32_t smem_u32(const void* p) {
    uint32_t a;
    asm("{ .reg .u64 t; cvta.to.shared.u64 t, %1; cvt.u32.u64 %0, t; }"
        : "=r"(a) : "l"(p));
    return a;
}
#define CP_ASYNC16(dst, src) \
    asm volatile("cp.async.cg.shared.global [%0], [%1], 16;" :: "r"(dst), "l"(src) : "memory")
#define CP_COMMIT() asm volatile("cp.async.commit_group;" ::: "memory")
#define CP_WAIT0()  asm volatile("cp.async.wait_group 0;"  ::: "memory")

#define LDMX4(r0,r1,r2,r3,addr) \
    asm volatile("ldmatrix.sync.aligned.m8n8.x4.shared.b16 {%0,%1,%2,%3}, [%4];" \
        : "=r"(r0),"=r"(r1),"=r"(r2),"=r"(r3) : "r"(addr))

#define MMA16816(c, a, b) \
    asm volatile("mma.sync.aligned.m16n8k16.row.col.f32.f16.f16.f32 " \
        "{%0,%1,%2,%3}, {%4,%5,%6,%7}, {%8,%9}, {%0,%1,%2,%3};" \
        : "+f"((c)[0]),"+f"((c)[1]),"+f"((c)[2]),"+f"((c)[3]) \
        : "r"((a)[0]),"r"((a)[1]),"r"((a)[2]),"r"((a)[3]), \
          "r"((b)[0]),"r"((b)[1]))

// ---------------------------------------------------------------------------
// Hi-only GEMM core: 128x128 tile, BK=32, 256 threads (8 warps 2x4, warp
// tile 64x32), acc += A@W per K-chunk. Single-sync 2-stage cp.async double
// buffer, 80B-padded rows, 2 CTAs/SM.
// ---------------------------------------------------------------------------
#define ROWB   80
#define TILEB  (128*ROWB)           // 10240 per tile
#define STAGEB (2*TILEB)            // 20480 per stage (A, W)
#define GEMM_SMEM (2*STAGEB)        // 40960

struct Pair { const char *a, *b; };

struct GemmCore {
    uint32_t sbase;
    int tid, lid, wid, wm, wn;
    size_t rowA0, rowB0;
    float acc[4][4][4];

    __device__ __forceinline__ void init(uint32_t sb, size_t ra0, size_t rb0) {
        sbase = sb;
        tid = threadIdx.x; lid = tid & 31; wid = tid >> 5;
        wm = (wid >> 2) * 64; wn = (wid & 3) * 32;
        rowA0 = ra0; rowB0 = rb0;
        #pragma unroll
        for (int i = 0; i < 4; i++)
            #pragma unroll
            for (int j = 0; j < 4; j++)
                #pragma unroll
                for (int q = 0; q < 4; q++) acc[i][j][q] = 0.0f;
    }

    __device__ __forceinline__ void load_stage(int stage, Pair t, int kb) {
        const uint32_t s0 = sbase + stage * STAGEB;
        #pragma unroll
        for (int i = 0; i < 2; i++) {
            int c = tid + i * 256;          // 0..511
            int r = c >> 2;                 // row 0..127
            int cc = (c & 3) * 16;          // 0/16/32/48
            uint32_t sp = r * ROWB + cc;
            CP_ASYNC16(s0 + sp,         t.a + (rowA0 + r) * 2048 + kb + cc);
            CP_ASYNC16(s0 + TILEB + sp, t.b + (rowB0 + r) * 2048 + kb + cc);
        }
    }

    __device__ __forceinline__ void compute_stage(int stage) {
        const uint32_t sA = sbase + stage * STAGEB;
        const uint32_t sB = sA + TILEB;
        #pragma unroll
        for (int kh = 0; kh < 2; kh++) {
            const uint32_t kho = kh * 32 + ((lid & 16) ? 16 : 0);
            const uint32_t khb = kh * 32 + (((lid >> 3) & 1) ? 16 : 0);
            const uint32_t arow = (uint32_t)(wm + (lid & 15)) * ROWB;
            const uint32_t brow = (uint32_t)(wn + ((lid >> 4) & 1) * 8 + (lid & 7)) * ROWB;

            uint32_t b[4][2];
            #pragma unroll
            for (int np = 0; np < 2; np++) {
                uint32_t r0, r1, r2, r3;
                LDMX4(r0, r1, r2, r3, sB + brow + np*16*ROWB + khb);
                b[np*2][0] = r0; b[np*2][1] = r1;
                b[np*2+1][0] = r2; b[np*2+1][1] = r3;
            }
            uint32_t a[4][4];
            #pragma unroll
            for (int mt = 0; mt < 4; mt++)
                LDMX4(a[mt][0], a[mt][1], a[mt][2], a[mt][3],
                      sA + arow + mt*16*ROWB + kho);
            #pragma unroll
            for (int mt = 0; mt < 4; mt++)
                #pragma unroll
                for (int nt = 0; nt < 4; nt++)
                    MMA16816(acc[mt][nt], a[mt], b[nt]);
        }
    }

    __device__ __forceinline__ void run(const Pair* terms, int nterms) {
        const int KTOT = nterms * 32;
        load_stage(0, terms[0], 0); CP_COMMIT();
        for (int k = 0; k < KTOT; k++) {
            CP_WAIT0();
            __syncthreads();
            int kn = k + 1;
            if (kn < KTOT) {
                load_stage(kn & 1, terms[kn >> 5], (kn & 31) * 64);
                CP_COMMIT();
            }
            compute_stage(k & 1);
        }
    }

    // mode 0: fp32 out; mode 2: single fp16 out
    __device__ __forceinline__ void epilogue(void* Cv, int Nout, int tileN,
                                             const float* colscale, int mode) {
        const int blockRow = blockIdx.y * 128;
        const int blockCol = tileN * 128;
        #pragma unroll
        for (int nt = 0; nt < 4; nt++) {
            int j = blockCol + wn + nt * 8 + (lid & 3) * 2;
            float cs0 = colscale ? colscale[j]     : 1.0f;
            float cs1 = colscale ? colscale[j + 1] : 1.0f;
            #pragma unroll
            for (int mt = 0; mt < 4; mt++) {
                int r = blockRow + wm + mt * 16 + (lid >> 2);
                float v00 = acc[mt][nt][0] * cs0, v01 = acc[mt][nt][1] * cs1;
                float v10 = acc[mt][nt][2] * cs0, v11 = acc[mt][nt][3] * cs1;
                if (mode == 0) {
                    float* C = (float*)Cv;
                    *(float2*)&C[(size_t)r * Nout + j]       = make_float2(v00, v01);
                    *(float2*)&C[(size_t)(r + 8) * Nout + j] = make_float2(v10, v11);
                } else {
                    __half* C = (__half*)Cv;
                    *(__half2*)&C[(size_t)r * Nout + j]       = __floats2half2_rn(v00, v01);
                    *(__half2*)&C[(size_t)(r + 8) * Nout + j] = __floats2half2_rn(v10, v11);
                }
            }
        }
    }
};

// ---------------------------------------------------------------------------
// Multi-job GEMM: shared A; grid.x = 8*njobs (tileN = blockIdx.x&7).
// ---------------------------------------------------------------------------
struct Job { const __half* b; void* out; const float* cs; int mode; };
struct MultiParams { const __half* a; Job jobs[3]; };

__global__ __launch_bounds__(256, 2)
void gemm_multi(MultiParams p, int Nout)
{
    extern __shared__ char smem[];
    const int g = blockIdx.x >> 3;
    const int tileN = blockIdx.x & 7;
    const Job jb = p.jobs[g];

    GemmCore core;
    core.init(smem_u32(smem), (size_t)blockIdx.y * 128, (size_t)tileN * 128);

    Pair t = { (const char*)p.a, (const char*)jb.b };
    core.run(&t, 1);
    core.epilogue(jb.out, Nout, tileN, jb.cs, jb.mode);
}

// ---------------------------------------------------------------------------
// 3-term GEMM (y)
// ---------------------------------------------------------------------------
struct GemmTerm { const __half *a, *b; };
struct YParams { GemmTerm t[3]; };

__global__ __launch_bounds__(256, 2)
void gemm_y(YParams p, float* __restrict__ C, int Nout)
{
    extern __shared__ char smem[];
    const int tileN = blockIdx.x;

    GemmCore core;
    core.init(smem_u32(smem), (size_t)blockIdx.y * 128, (size_t)tileN * 128);

    Pair t[3];
    #pragma unroll
    for (int i = 0; i < 3; i++)
        t[i] = { (const char*)p.t[i].a, (const char*)p.t[i].b };
    core.run(t, 3);
    core.epilogue(C, Nout, tileN, nullptr, 0);
}

// ---------------------------------------------------------------------------
// Per-channel recurrence parameters
// ---------------------------------------------------------------------------
__global__ void params_kernel(const float* __restrict__ nu_log,
                              const float* __restrict__ theta_log)
{
    int n = blockIdx.x * blockDim.x + threadIdx.x;
    if (n < NN) {
        float mag   = expf(-expf(nu_log[n]));
        float phase = expf(theta_log[n]);
        g_lam[n]        = mag * cosf(phase);
        g_lam[NN + n]   = mag * sinf(phase);
        g_lam[2*NN + n] = sqrtf(fmaxf(1.0f - mag*mag, 0.0f));
    }
}

// ---------------------------------------------------------------------------
// Vectorized fp32 -> fp16 conversions
// ---------------------------------------------------------------------------
__device__ __forceinline__ uint32_t pack2h(float a, float b)
{
    return (uint32_t)__half_as_ushort(__float2half(a))
         | ((uint32_t)__half_as_ushort(__float2half(b)) << 16);
}

__global__ void cvt_x4(const float4* __restrict__ src,
                       uint2* __restrict__ dst, int n4)
{
    int i = blockIdx.x * blockDim.x + threadIdx.x;
    if (i < n4) {
        float4 f = src[i];
        uint2 o;
        o.x = pack2h(f.x, f.y);
        o.y = pack2h(f.z, f.w);
        dst[i] = o;
    }
}

// All 7 weights -> single fp16; slice 3 (C_im) negated.
struct WPtrs { const float* p[7]; };
__global__ void cvt_w4(WPtrs wp, uint2* __restrict__ out)
{
    int i = blockIdx.x * blockDim.x + threadIdx.x;      // 0 .. 7*WSZ/4-1
    int w = i / (WSZ/4);
    int j = i - w * (WSZ/4);
    float4 f = ((const float4*)wp.p[w])[j];
    if (w == 3) { f.x = -f.x; f.y = -f.y; f.z = -f.z; f.w = -f.w; }
    uint2 o;
    o.x = pack2h(f.x, f.y);
    o.y = pack2h(f.z, f.w);
    out[i] = o;
}

// ---------------------------------------------------------------------------
// Sequential complex recurrence, blocked by 16; u single fp16; hs single fp16.
// ---------------------------------------------------------------------------
__global__ void scan_kernel(const float* __restrict__ hid_re,
                            const float* __restrict__ hid_im,
                            float* __restrict__ out)
{
    int idx = blockIdx.x * blockDim.x + threadIdx.x;   // 0..B*N-1
    int b = idx >> 10;
    int n = idx & (NN - 1);
    const float lre = g_lam[n];
    const float lim = g_lam[NN + n];
    float hr = hid_re[idx];
    float hi = hid_im[idx];
    size_t off = (size_t)b * SS * NN + n;
    for (int s0 = 0; s0 < SS; s0 += 16) {
        __half pur[16], pui[16];
        #pragma unroll
        for (int q = 0; q < 16; q++) {
            pur[q] = g_u_re[off + (size_t)q * NN];
            pui[q] = g_u_im[off + (size_t)q * NN];
        }
        #pragma unroll
        for (int q = 0; q < 16; q++) {
            float nr = fmaf(lre, hr, fmaf(-lim, hi, __half2float(pur[q])));
            float ni = fmaf(lre, hi, fmaf( lim, hr, __half2float(pui[q])));
            size_t o = off + (size_t)q * NN;
            g_hsre[o] = __float2half(nr);
            g_hsim[o] = __float2half(ni);
            hr = nr; hi = ni;
        }
        off += (size_t)16 * NN;
    }
    out[(size_t)MM * DD + idx]         = hr;   // hf_re
    out[(size_t)MM * DD + BB*NN + idx] = hi;   // hf_im
}

// ---------------------------------------------------------------------------
// Fused pointwise: z = gelu(LN(LN(y) * gelu(LN(g)))) -> single fp16
// ---------------------------------------------------------------------------
__device__ __forceinline__ float gelu_exact(float x)
{
    return 0.5f * x * (1.0f + erff(x * 0.70710678118654752f));
}
__device__ __forceinline__ void block_stats(float v0, float v1, float v2, float v3,
                                            float* sh, float& mu, float& rstd)
{
    float s  = v0 + v1 + v2 + v3;
    float s2 = v0*v0 + v1*v1 + v2*v2 + v3*v3;
    #pragma unroll
    for (int o = 16; o > 0; o >>= 1) {
        s  += __shfl_xor_sync(0xffffffffu, s,  o);
        s2 += __shfl_xor_sync(0xffffffffu, s2, o);
    }
    int w = threadIdx.x >> 5, l = threadIdx.x & 31;
    if (l == 0) { sh[w] = s; sh[8 + w] = s2; }
    __syncthreads();
    float ts = 0.f, ts2 = 0.f;
    #pragma unroll
    for (int i = 0; i < 8; i++) { ts += sh[i]; ts2 += sh[8 + i]; }
    __syncthreads();
    mu = ts * (1.0f / NN);
    float var = ts2 * (1.0f / NN) - mu * mu;
    rstd = rsqrtf(var + 1e-5f);
}

__global__ __launch_bounds__(256)
void pointwise_kernel(const float* __restrict__ y, const float* __restrict__ g)
{
    __shared__ float sh[16];
    const size_t base = (size_t)blockIdx.x * NN;
    const int t = threadIdx.x;

    float yv[4], gv[4];
    #pragma unroll
    for (int q = 0; q < 4; q++) {
        yv[q] = y[base + t + q*256];
        gv[q] = g[base + t + q*256];
    }
    float mu, rstd;
    block_stats(yv[0], yv[1], yv[2], yv[3], sh, mu, rstd);
    #pragma unroll
    for (int q = 0; q < 4; q++) yv[q] = (yv[q] - mu) * rstd;
    block_stats(gv[0], gv[1], gv[2], gv[3], sh, mu, rstd);
    #pragma unroll
    for (int q = 0; q < 4; q++) gv[q] = gelu_exact((gv[q] - mu) * rstd);
    #pragma unroll
    for (int q = 0; q < 4; q++) yv[q] *= gv[q];
    block_stats(yv[0], yv[1], yv[2], yv[3], sh, mu, rstd);
    #pragma unroll
    for (int q = 0; q < 4; q++)
        g_z[base + t + q*256] = __float2half(gelu_exact((yv[q] - mu) * rstd));
}

// ---------------------------------------------------------------------------
// Launch.  ncu capture lands on launch index 3 -> big gemm_multi there.
// ---------------------------------------------------------------------------
extern "C" void kernel_launch(void* const* d_in, const int* in_sizes, int n_in,
                              void* d_out, int out_size)
{
    const float* x         = (const float*)d_in[0];
    const float* hidden_re = (const float*)d_in[1];
    const float* hidden_im = (const float*)d_in[2];
    const float* nu_log    = (const float*)d_in[3];
    const float* theta_log = (const float*)d_in[4];
    float* out = (float*)d_out;

    __half *u_re, *u_im, *xbuf, *hsre, *hsim, *zbuf, *wbuf;
    float *ybuf, *gbuf, *lam;
    cudaGetSymbolAddress((void**)&u_re, g_u_re);
    cudaGetSymbolAddress((void**)&u_im, g_u_im);
    cudaGetSymbolAddress((void**)&ybuf, g_y);
    cudaGetSymbolAddress((void**)&gbuf, g_g);
    cudaGetSymbolAddress((void**)&xbuf, g_x);
    cudaGetSymbolAddress((void**)&hsre, g_hsre);
    cudaGetSymbolAddress((void**)&hsim, g_hsim);
    cudaGetSymbolAddress((void**)&zbuf, g_z);
    cudaGetSymbolAddress((void**)&wbuf, g_w);
    cudaGetSymbolAddress((void**)&lam,  g_lam);
    const float* gamma = lam + 2*NN;

    cudaFuncSetAttribute(gemm_multi, cudaFuncAttributeMaxDynamicSharedMemorySize, GEMM_SMEM);
    cudaFuncSetAttribute(gemm_y,     cudaFuncAttributeMaxDynamicSharedMemorySize, GEMM_SMEM);

    params_kernel<<<1, 1024>>>(nu_log, theta_log);                       // idx 0
    {
        int n4 = MM*DD/4;
        cvt_x4<<<(n4 + 255)/256, 256>>>((const float4*)x, (uint2*)xbuf, n4); // idx 1
    }
    {
        WPtrs wp;
        for (int w = 0; w < 7; w++) wp.p[w] = (const float*)d_in[5 + w];
        cvt_w4<<<(7*WSZ/4 + 255)/256, 256>>>(wp, (uint2*)wbuf);          // idx 2
    }

    // idx 3 (ncu capture target): fused u_re / u_im / gate GEMM (hi-only)
    MultiParams mp;
    mp.a = xbuf;
    mp.jobs[0] = { wbuf + (size_t)0*WSZ, (void*)u_re, gamma,   2 };
    mp.jobs[1] = { wbuf + (size_t)1*WSZ, (void*)u_im, gamma,   2 };
    mp.jobs[2] = { wbuf + (size_t)5*WSZ, (void*)gbuf, nullptr, 0 };
    gemm_multi<<<dim3(24, MM/128), 256, GEMM_SMEM>>>(mp, NN);

    // idx 4: recurrence (consumes u, writes hs single-fp16 + final state)
    scan_kernel<<<(BB*NN)/256, 256>>>(hidden_re, hidden_im, out);

    // idx 5: y = hs_re@C_re^T - hs_im@C_im^T + x@D_skip^T
    YParams py;
    py.t[0] = { hsre, wbuf + (size_t)2*WSZ };
    py.t[1] = { hsim, wbuf + (size_t)3*WSZ };
    py.t[2] = { xbuf, wbuf + (size_t)4*WSZ };
    gemm_y<<<dim3(8, MM/128), 256, GEMM_SMEM>>>(py, ybuf, NN);

    // idx 6: fused LN/GELU chain -> z single fp16
    pointwise_kernel<<<MM, 256>>>(ybuf, gbuf);

    // idx 7: out = z @ W_con^T
    MultiParams mo;
    mo.a = zbuf;
    mo.jobs[0] = { wbuf + (size_t)6*WSZ, (void*)out, nullptr, 0 };
    gemm_multi<<<dim3(8, MM/128), 256, GEMM_SMEM>>>(mo, DD);
}